// round 14
// baseline (speedup 1.0000x reference)
#include <cuda_runtime.h>
#include <math.h>

#define N_NODES 50000
#define N_EDGES 400000
#define HID 64
#define F_IN 8
#define NL 3

// padded dims
#define K1 132    // e_in padded (130 -> 132)
#define N1 288    // edge hidden padded (260 -> 288)
#define K2 260    // GEMM2 true K
#define NPAD 50048

#define ETILE 48  // edges per block
#define TPB 256

// ---------------- device scratch (no allocations allowed) ----------------
__device__ float g_feats[N_NODES * HID];
__device__ float g_coors[N_NODES * 3];
__device__ float g_magg[N_NODES * HID];
__device__ float g_cdelta[N_NODES * 3];
__device__ float g_eW1p[NL * K1 * N1];
__device__ float g_eb1p[NL * N1];
__device__ float g_PA[NPAD * N1];   // feats @ W1a + b1 (per current layer)
__device__ float g_PB[NPAD * N1];   // feats @ W1b
__device__ float g_zbias[N1];       // stays zero (device globals zero-init)
// eW2 k-pair-interleaved: [l][k/2][n] -> (w_k, w_{k+1}) as 2 floats
__device__ float g_eW2i[NL * 130 * 64 * 2];

__device__ __forceinline__ float silu_f(float v) {
    return v * __fdividef(1.0f, 1.0f + __expf(-v));
}

// packed f32x2 helpers (sm_103a FFMA2 path — only reachable via PTX)
typedef unsigned long long u64;
__device__ __forceinline__ u64 packdup(float x) {
    u64 r;
    asm("mov.b64 %0, {%1, %1};" : "=l"(r) : "r"(__float_as_uint(x)));
    return r;
}
__device__ __forceinline__ u64 pack2(float x, float y) {
    u64 r;
    asm("mov.b64 %0, {%1, %2};" : "=l"(r)
        : "r"(__float_as_uint(x)), "r"(__float_as_uint(y)));
    return r;
}
__device__ __forceinline__ float2 unpackf2(u64 v) {
    unsigned int lo, hi;
    asm("mov.b64 {%0, %1}, %2;" : "=r"(lo), "=r"(hi) : "l"(v));
    return make_float2(__uint_as_float(lo), __uint_as_float(hi));
}
#define FFMA2(acc, a, w) \
    asm("fma.rn.f32x2 %0, %1, %2, %0;" : "+l"(acc) : "l"(a), "l"(w))

// cp.async 16B helpers (LDGSTS — register-free weight staging)
__device__ __forceinline__ void cp16(float* dst_smem, const float* src) {
    unsigned int a = (unsigned int)__cvta_generic_to_shared(dst_smem);
    asm volatile("cp.async.cg.shared.global [%0], [%1], 16;" :: "r"(a), "l"(src));
}
#define CP_COMMIT() asm volatile("cp.async.commit_group;" ::: "memory")
#define CP_WAIT0()  asm volatile("cp.async.wait_group 0;" ::: "memory")

// ---------------- generic GEMM tile (unchanged R13 path) ----------------
template<int K, int N, int KC, int AS, int CS, int P, int R, bool ACT, int RPT,
         int TPBT>
__device__ __forceinline__ void gemm_tile(const float* __restrict__ A,
                                          const float* __restrict__ Wg,
                                          const float* __restrict__ Bg,
                                          float* __restrict__ C,
                                          float* __restrict__ Wst)
{
    static_assert(KC % 4 == 0, "KC must be a multiple of 4");
    constexpr int NCHUNK = K / KC;
    constexpr int CHSZ = KC * N;
    constexpr int NLD = CHSZ / 4;
    const int tid = threadIdx.x;
    const int er = tid >> 5;
    const int cc = tid & 31;

    u64 accp[RPT][P];
    float accs[RPT];
#pragma unroll
    for (int i = 0; i < RPT; i++) {
        accs[i] = 0.0f;
#pragma unroll
        for (int p = 0; p < P; p++) accp[i][p] = 0ULL;
    }

    for (int i = tid; i < NLD; i += TPBT) cp16(Wst + 4 * i, Wg + 4 * i);
    CP_COMMIT();
    CP_WAIT0();
    __syncthreads();

    for (int c = 0; c < NCHUNK; c++) {
        const float* buf = Wst + (c & 1) * CHSZ;
        float* nbuf = Wst + ((c + 1) & 1) * CHSZ;
        if (c + 1 < NCHUNK) {
            const float* src = Wg + (c + 1) * CHSZ;
            for (int i = tid; i < NLD; i += TPBT) cp16(nbuf + 4 * i, src + 4 * i);
            CP_COMMIT();
        }
        const int k0 = c * KC;

        u64 wc[P], wn[P];
        float wsc = 0.0f, wsn = 0.0f;
#pragma unroll
        for (int p = 0; p < P; p++) wc[p] = *(const u64*)(buf + 2 * cc + 64 * p);
        if (R) wsc = buf[64 * P + cc];

#pragma unroll
        for (int kk = 0; kk < KC; kk += 4) {
            float4 a4[RPT];
#pragma unroll
            for (int i = 0; i < RPT; i++)
                a4[i] = *(const float4*)(A + (er * RPT + i) * AS + k0 + kk);
#pragma unroll
            for (int k = 0; k < 4; k++) {
                const int kn = kk + k + 1;
                if (kn < KC) {
#pragma unroll
                    for (int p = 0; p < P; p++)
                        wn[p] = *(const u64*)(buf + kn * N + 2 * cc + 64 * p);
                    if (R) wsn = buf[kn * N + 64 * P + cc];
                }
#pragma unroll
                for (int i = 0; i < RPT; i++) {
                    float av = (k == 0) ? a4[i].x : (k == 1) ? a4[i].y
                             : (k == 2) ? a4[i].z : a4[i].w;
                    u64 ad = packdup(av);
#pragma unroll
                    for (int p = 0; p < P; p++) FFMA2(accp[i][p], ad, wc[p]);
                    if (R) accs[i] = fmaf(av, wsc, accs[i]);
                }
#pragma unroll
                for (int p = 0; p < P; p++) wc[p] = wn[p];
                if (R) wsc = wsn;
            }
        }
        if (c + 1 < NCHUNK) CP_WAIT0();
        __syncthreads();
    }

    float2 bv[P];
    float bs = 0.0f;
#pragma unroll
    for (int p = 0; p < P; p++) bv[p] = *(const float2*)(Bg + 2 * cc + 64 * p);
    if (R) bs = Bg[64 * P + cc];
#pragma unroll
    for (int i = 0; i < RPT; i++) {
#pragma unroll
        for (int p = 0; p < P; p++) {
            float2 v = unpackf2(accp[i][p]);
            v.x += bv[p].x;
            v.y += bv[p].y;
            if (ACT) { v.x = silu_f(v.x); v.y = silu_f(v.y); }
            *(float2*)(C + (er * RPT + i) * CS + 2 * cc + 64 * p) = v;
        }
        if (R) {
            float v = accs[i] + bs;
            if (ACT) v = silu_f(v);
            C[(er * RPT + i) * CS + 64 * P + cc] = v;
        }
    }
}

// ---------------- GEMM2 k-pair tile: m = silu(h1 @ eW2i + b) --------------
// K=260 (130 k-pairs, 5 chunks of 26 pairs), N=64. Thread (er,cc):
// rows er*6..er*6+5, cols cc and cc+32. acc2 lanes = (k-even, k-odd) partial
// sums; C = lo+hi at epilogue. Wg is the k-interleaved copy ([k2][n][2]).
// No packdup: A pairs repacked from float4 broadcasts, W pairs loaded as u64.
__device__ __forceinline__ void gemm2_kpair(const float* __restrict__ A,
                                            const float* __restrict__ Wg,
                                            const float* __restrict__ Bg,
                                            float* __restrict__ C,
                                            float* __restrict__ Wst)
{
    constexpr int KP = 26;            // k-pairs per chunk
    constexpr int CHSZ = KP * 128;    // floats per chunk (26*64*2 = 3328)
    constexpr int NLD = CHSZ / 4;     // 832
    const int tid = threadIdx.x;
    const int er = tid >> 5;
    const int cc = tid & 31;

    u64 acc[6][2];
#pragma unroll
    for (int i = 0; i < 6; i++) { acc[i][0] = 0ULL; acc[i][1] = 0ULL; }

    for (int i = tid; i < NLD; i += TPB) cp16(Wst + 4 * i, Wg + 4 * i);
    CP_COMMIT();
    CP_WAIT0();
    __syncthreads();

    for (int c = 0; c < 5; c++) {
        const float* buf = Wst + (c & 1) * CHSZ;
        float* nbuf = Wst + ((c + 1) & 1) * CHSZ;
        if (c + 1 < 5) {
            const float* src = Wg + (c + 1) * CHSZ;
            for (int i = tid; i < NLD; i += TPB) cp16(nbuf + 4 * i, src + 4 * i);
            CP_COMMIT();
        }
        const int k0 = c * 52;

        // W k-pair double-buffer, primed with local pair 0
        u64 wc0 = *(const u64*)(buf + cc * 2);
        u64 wc1 = *(const u64*)(buf + (cc + 32) * 2);
        u64 wn0, wn1;

#pragma unroll
        for (int kk2 = 0; kk2 < KP; kk2 += 2) {
            float4 a4[6];
#pragma unroll
            for (int i = 0; i < 6; i++)
                a4[i] = *(const float4*)(A + (er * 6 + i) * N1 + k0 + kk2 * 2);
#pragma unroll
            for (int h = 0; h < 2; h++) {
                const int nk2 = kk2 + h + 1;
                if (nk2 < KP) {
                    wn0 = *(const u64*)(buf + (nk2 * 64 + cc) * 2);
                    wn1 = *(const u64*)(buf + (nk2 * 64 + cc + 32) * 2);
                }
#pragma unroll
                for (int i = 0; i < 6; i++) {
                    u64 ap = h ? pack2(a4[i].z, a4[i].w)
                               : pack2(a4[i].x, a4[i].y);
                    FFMA2(acc[i][0], ap, wc0);
                    FFMA2(acc[i][1], ap, wc1);
                }
                wc0 = wn0;
                wc1 = wn1;
            }
        }
        if (c + 1 < 5) CP_WAIT0();
        __syncthreads();
    }

    // epilogue: C[r][c] = silu(lo + hi + bias)
    float b0 = Bg[cc], b1 = Bg[cc + 32];
#pragma unroll
    for (int i = 0; i < 6; i++) {
        float2 v0 = unpackf2(acc[i][0]);
        float2 v1 = unpackf2(acc[i][1]);
        C[(er * 6 + i) * 64 + cc]      = silu_f(v0.x + v0.y + b0);
        C[(er * 6 + i) * 64 + cc + 32] = silu_f(v1.x + v1.y + b1);
    }
}

// ---------------- GEMM + fused dot tile (unchanged R13 path) --------------
template<int K, int N, int KC, int AS, int P, int RPT, int TPBT>
__device__ __forceinline__ void gemm_dot_tile(const float* __restrict__ A,
                                              const float* __restrict__ Wg,
                                              const float* __restrict__ Bg,
                                              const float* __restrict__ sdot,
                                              float* __restrict__ cwout,
                                              float* __restrict__ Wst)
{
    static_assert(KC % 4 == 0, "KC must be a multiple of 4");
    constexpr int NCHUNK = K / KC;
    constexpr int CHSZ = KC * N;
    constexpr int NLD = CHSZ / 4;
    const int tid = threadIdx.x;
    const int er = tid >> 5;
    const int cc = tid & 31;

    u64 accp[RPT][P];
#pragma unroll
    for (int i = 0; i < RPT; i++)
#pragma unroll
        for (int p = 0; p < P; p++) accp[i][p] = 0ULL;

    for (int i = tid; i < NLD; i += TPBT) cp16(Wst + 4 * i, Wg + 4 * i);
    CP_COMMIT();
    CP_WAIT0();
    __syncthreads();

    for (int c = 0; c < NCHUNK; c++) {
        const float* buf = Wst + (c & 1) * CHSZ;
        float* nbuf = Wst + ((c + 1) & 1) * CHSZ;
        if (c + 1 < NCHUNK) {
            const float* src = Wg + (c + 1) * CHSZ;
            for (int i = tid; i < NLD; i += TPBT) cp16(nbuf + 4 * i, src + 4 * i);
            CP_COMMIT();
        }
        const int k0 = c * KC;

        u64 wc[P], wn[P];
#pragma unroll
        for (int p = 0; p < P; p++) wc[p] = *(const u64*)(buf + 2 * cc + 64 * p);

#pragma unroll
        for (int kk = 0; kk < KC; kk += 4) {
            float4 a4[RPT];
#pragma unroll
            for (int i = 0; i < RPT; i++)
                a4[i] = *(const float4*)(A + (er * RPT + i) * AS + k0 + kk);
#pragma unroll
            for (int k = 0; k < 4; k++) {
                const int kn = kk + k + 1;
                if (kn < KC) {
#pragma unroll
                    for (int p = 0; p < P; p++)
                        wn[p] = *(const u64*)(buf + kn * N + 2 * cc + 64 * p);
                }
#pragma unroll
                for (int i = 0; i < RPT; i++) {
                    float av = (k == 0) ? a4[i].x : (k == 1) ? a4[i].y
                             : (k == 2) ? a4[i].z : a4[i].w;
                    u64 ad = packdup(av);
#pragma unroll
                    for (int p = 0; p < P; p++) FFMA2(accp[i][p], ad, wc[p]);
                }
#pragma unroll
                for (int p = 0; p < P; p++) wc[p] = wn[p];
            }
        }
        if (c + 1 < NCHUNK) CP_WAIT0();
        __syncthreads();
    }

    float2 bv[P], dv[P];
#pragma unroll
    for (int p = 0; p < P; p++) {
        bv[p] = *(const float2*)(Bg + 2 * cc + 64 * p);
        dv[p] = *(const float2*)(sdot + 2 * cc + 64 * p);
    }
#pragma unroll
    for (int i = 0; i < RPT; i++) {
        float s = 0.0f;
#pragma unroll
        for (int p = 0; p < P; p++) {
            float2 v = unpackf2(accp[i][p]);
            s += silu_f(v.x + bv[p].x) * dv[p].x;
            s += silu_f(v.y + bv[p].y) * dv[p].y;
        }
#pragma unroll
        for (int o = 16; o > 0; o >>= 1) s += __shfl_xor_sync(0xFFFFFFFFu, s, o);
        if (cc == 0) cwout[er * RPT + i] = s;
    }
}

// ---------------- weight padding / prep ----------------
__global__ void __launch_bounds__(256) pad_kernel(const float* __restrict__ eW1,
                                                  const float* __restrict__ eb1,
                                                  const float* __restrict__ eW2)
{
    const int A = NL * K1 * N1;
    const int B = NL * N1;
    const int Cc = NL * K2 * 64;   // eW2 interleave
    int i = blockIdx.x * 256 + threadIdx.x;
    if (i < A) {
        int l = i / (K1 * N1);
        int r = (i / N1) % K1;
        int j = i % N1;
        g_eW1p[i] = (r < 130 && j < 260) ? eW1[(l * 130 + r) * 260 + j] : 0.0f;
    } else if (i < A + B) {
        int ii = i - A;
        int l = ii / N1, j = ii % N1;
        g_eb1p[ii] = (j < 260) ? eb1[l * 260 + j] : 0.0f;
    } else if (i < A + B + Cc) {
        int ii = i - A - B;
        int l = ii / (K2 * 64);
        int r = ii % (K2 * 64);
        int k = r / 64, n = r % 64;
        g_eW2i[((l * 130 + (k >> 1)) * 64 + n) * 2 + (k & 1)] =
            eW2[(l * K2 + k) * 64 + n];
    }
}

// ---------------- embed + pos copy ----------------
__global__ void __launch_bounds__(256) embed_kernel(const float* __restrict__ x,
                                                    const float* __restrict__ pos,
                                                    const float* __restrict__ W,
                                                    const float* __restrict__ b)
{
    int idx = blockIdx.x * 256 + threadIdx.x;
    if (idx < N_NODES * 3) g_coors[idx] = pos[idx];
    if (idx < N_NODES * HID) {
        int n = idx >> 6, j = idx & 63;
        float acc = b[j];
#pragma unroll
        for (int k = 0; k < F_IN; k++) acc = fmaf(x[n * F_IN + k], W[k * HID + j], acc);
        g_feats[idx] = acc;
    }
}

// ---------------- per-node precompute (+ zero of agg buffers) ----------------
#define PRE_SMEM_F 13312

__global__ void __launch_bounds__(256, 2) prenode_kernel(int l)
{
    extern __shared__ float sm[];
    float* sF = sm;
    float* Wst = sm + 4096;

    const int tid = threadIdx.x;
    const int n0 = blockIdx.x * 64;

    for (int idx = tid; idx < 64 * 64; idx += TPB) {
        int nl = idx >> 6, k = idx & 63;
        int n = n0 + nl;
        float f = 0.0f;
        if (n < N_NODES) {
            f = g_feats[n * HID + k];
            g_magg[n * HID + k] = 0.0f;
        }
        sF[idx] = f;
    }
    if (tid < 192) {
        int n = n0 + tid / 3;
        int d = tid % 3;
        if (n < N_NODES) g_cdelta[n * 3 + d] = 0.0f;
    }

    const float* W1 = g_eW1p + l * K1 * N1;
    gemm_tile<64, N1, 16, 64, N1, 4, 1, false, 8, TPB>(sF, W1, g_eb1p + l * N1,
                                                       g_PA + n0 * N1, Wst);
    gemm_tile<64, N1, 16, 64, N1, 4, 1, false, 8, TPB>(sF, W1 + 64 * N1, g_zbias,
                                                       g_PB + n0 * N1, Wst);
}

// ---------------- edge kernel (48 edges/block, 256 threads, 2 CTA/SM) -----
#define EDGE_SMEM_F 26304

__global__ void __launch_bounds__(256, 2) edge_kernel(const int* __restrict__ ei,
                                                      const float* __restrict__ eattr,
                                                      const float* __restrict__ eb2,
                                                      const float* __restrict__ cW1,
                                                      const float* __restrict__ cb1,
                                                      const float* __restrict__ cW2,
                                                      const float* __restrict__ cb2,
                                                      int l)
{
    extern __shared__ float sm[];
    float* R1 = sm;
    float* mT = sm + 13824;
    float* Wst = sm + 16896;
    float* sWea = sm + 25088;
    float* sWdist = sm + 25376;
    float* scw = sm + 25664;
    int* srow = (int*)(sm + 25712);
    int* scol = (int*)(sm + 25760);
    float* srel = sm + 25808;
    float* sea = sm + 26000;
    float* sdot = sm + 26048;

    const int tid = threadIdx.x;
    const int e0 = blockIdx.x * ETILE;

    // phase 0a: scalars + small weight vectors
    sdot[tid] = cW2[l * 256 + tid];
    {
        const float* Wea = g_eW1p + l * K1 * N1 + 128 * N1;
        for (int idx = tid; idx < 2 * N1; idx += TPB) {
            if (idx < N1) sWea[idx] = Wea[idx];
            else sWdist[idx - N1] = Wea[N1 + (idx - N1)];
        }
    }
    if (tid < ETILE) {
        int e = e0 + tid;
        int r = 0, c = 0;
        float ea = 0.0f;
        if (e < N_EDGES) {
            r = ei[e];
            c = ei[N_EDGES + e];
            ea = eattr[e];
        }
        srow[tid] = r;
        scol[tid] = c;
        float rx = g_coors[r * 3 + 0] - g_coors[c * 3 + 0];
        float ry = g_coors[r * 3 + 1] - g_coors[c * 3 + 1];
        float rz = g_coors[r * 3 + 2] - g_coors[c * 3 + 2];
        srel[tid * 4 + 0] = rx;
        srel[tid * 4 + 1] = ry;
        srel[tid * 4 + 2] = rz;
        srel[tid * 4 + 3] = rx * rx + ry * ry + rz * rz;
        sea[tid] = ea;
    }
    __syncthreads();

    // phase A: h1[e][0:260] = silu(PA[row] + PB[col] + ea*Wea + dist*Wdist)
    for (int idx = tid; idx < ETILE * 65; idx += TPB) {
        int e = idx / 65, q = idx - e * 65;
        float4 a = ((const float4*)(g_PA + srow[e] * N1))[q];
        float4 b = ((const float4*)(g_PB + scol[e] * N1))[q];
        float4 we = ((const float4*)sWea)[q];
        float4 wd = ((const float4*)sWdist)[q];
        float ea = sea[e], di = srel[e * 4 + 3];
        float4 v;
        v.x = silu_f(fmaf(di, wd.x, fmaf(ea, we.x, a.x + b.x)));
        v.y = silu_f(fmaf(di, wd.y, fmaf(ea, we.y, a.y + b.y)));
        v.z = silu_f(fmaf(di, wd.z, fmaf(ea, we.z, a.z + b.z)));
        v.w = silu_f(fmaf(di, wd.w, fmaf(ea, we.w, a.w + b.w)));
        ((float4*)(R1 + e * N1))[q] = v;
    }

    // GEMM2 (k-pair FFMA2): m = silu(h1[:, :260] @ eW2 + eb2)
    gemm2_kpair(R1, g_eW2i + l * 130 * 64 * 2, eb2 + l * HID, mT, Wst);
    // GEMM3 + dot fused: scw[e] = silu(m @ cW1 + cb1) . cW2
    gemm_dot_tile<64, 256, 16, 64, 4, 6, TPB>(mT, cW1 + l * 64 * 256,
                                              cb1 + l * 256, sdot, scw, Wst);
    __syncthreads();

    // coords atomics
    if (tid < ETILE) {
        int e = tid;
        if (e0 + e < N_EDGES) {
            float cw = scw[e] + cb2[l];
            int r = srow[e];
            atomicAdd(&g_cdelta[r * 3 + 0], cw * srel[e * 4 + 0]);
            atomicAdd(&g_cdelta[r * 3 + 1], cw * srel[e * 4 + 1]);
            atomicAdd(&g_cdelta[r * 3 + 2], cw * srel[e * 4 + 2]);
        }
    }
    // scatter m into node aggregation
    for (int idx = tid; idx < ETILE * 64; idx += TPB) {
        int e = idx >> 6, k = idx & 63;
        if (e0 + e < N_EDGES)
            atomicAdd(&g_magg[srow[e] * HID + k], mT[e * 64 + k]);
    }
}

// ---------------- node kernel (64 nodes/block, 256 threads) ----------------
#define NODE_SMEM_F 24576

__global__ void __launch_bounds__(256, 2) node_kernel(const float* __restrict__ nW1,
                                                      const float* __restrict__ nb1,
                                                      const float* __restrict__ nW2,
                                                      const float* __restrict__ nb2,
                                                      int l)
{
    extern __shared__ float sm[];
    float* sH = sm;
    float* sT1 = sm + 8192;
    float* Wst = sm + 16384;

    const int tid = threadIdx.x;
    const int n0 = blockIdx.x * 64;

    for (int idx = tid; idx < 64 * 64; idx += TPB) {
        int nl = idx >> 6, k = idx & 63;
        int n = n0 + nl;
        float f = 0.0f, mg = 0.0f;
        if (n < N_NODES) { f = g_feats[n * HID + k]; mg = g_magg[n * HID + k]; }
        sH[nl * 128 + k] = f;
        sH[nl * 128 + 64 + k] = mg;
    }

    gemm_tile<128, 128, 32, 128, 128, 2, 0, true, 8, TPB>(sH, nW1 + l * 128 * 128,
                                                          nb1 + l * 128, sT1, Wst);
    gemm_tile<128, 64, 32, 128, 64, 1, 0, false, 8, TPB>(sT1, nW2 + l * 128 * 64,
                                                         nb2 + l * 64, sH, Wst);
    __syncthreads();

    for (int idx = tid; idx < 64 * 64; idx += TPB) {
        int nl = idx >> 6, k = idx & 63;
        int n = n0 + nl;
        if (n < N_NODES) g_feats[n * HID + k] += sH[idx];
    }
    if (tid < 192) {
        int n = n0 + tid / 3;
        int d = tid % 3;
        if (n < N_NODES) g_coors[n * 3 + d] += g_cdelta[n * 3 + d];
    }
}

// ---------------- final projection ----------------
__global__ void __launch_bounds__(256) final_kernel(const float* __restrict__ linW,
                                                    const float* __restrict__ linb,
                                                    float* __restrict__ out)
{
    int warp = (blockIdx.x * 256 + threadIdx.x) >> 5;
    int lane = threadIdx.x & 31;
    if (warp >= N_NODES) return;
    const float* f = g_feats + warp * HID;
    float s = fmaf(f[lane], linW[lane], f[lane + 32] * linW[lane + 32]);
#pragma unroll
    for (int o = 16; o > 0; o >>= 1) s += __shfl_xor_sync(0xFFFFFFFFu, s, o);
    if (lane == 0) out[warp] = s + linb[0];
}

// ---------------- launch ----------------
extern "C" void kernel_launch(void* const* d_in, const int* in_sizes, int n_in,
                              void* d_out, int out_size)
{
    const float* x      = (const float*)d_in[0];
    const float* pos    = (const float*)d_in[1];
    const int*   ei     = (const int*)  d_in[2];
    const float* eattr  = (const float*)d_in[3];
    const float* embedW = (const float*)d_in[4];
    const float* embedb = (const float*)d_in[5];
    const float* eW1    = (const float*)d_in[6];
    const float* eb1    = (const float*)d_in[7];
    const float* eW2    = (const float*)d_in[8];
    const float* eb2    = (const float*)d_in[9];
    const float* cW1    = (const float*)d_in[10];
    const float* cb1    = (const float*)d_in[11];
    const float* cW2    = (const float*)d_in[12];
    const float* cb2    = (const float*)d_in[13];
    const float* nW1    = (const float*)d_in[14];
    const float* nb1    = (const float*)d_in[15];
    const float* nW2    = (const float*)d_in[16];
    const float* nb2    = (const float*)d_in[17];
    const float* linW   = (const float*)d_in[18];
    const float* linb   = (const float*)d_in[19];
    float* out = (float*)d_out;

    cudaFuncSetAttribute(edge_kernel, cudaFuncAttributeMaxDynamicSharedMemorySize,
                         EDGE_SMEM_F * 4);
    cudaFuncSetAttribute(node_kernel, cudaFuncAttributeMaxDynamicSharedMemorySize,
                         NODE_SMEM_F * 4);
    cudaFuncSetAttribute(prenode_kernel, cudaFuncAttributeMaxDynamicSharedMemorySize,
                         PRE_SMEM_F * 4);

    {
        int total = NL * K1 * N1 + NL * N1 + NL * K2 * 64;
        pad_kernel<<<(total + 255) / 256, 256>>>(eW1, eb1, eW2);
    }
    embed_kernel<<<(N_NODES * HID + 255) / 256, 256>>>(x, pos, embedW, embedb);

    const int egrid = (N_EDGES + ETILE - 1) / ETILE;
    const int ngrid = (N_NODES + 63) / 64;
    for (int l = 0; l < NL; l++) {
        prenode_kernel<<<ngrid, TPB, PRE_SMEM_F * 4>>>(l);
        edge_kernel<<<egrid, TPB, EDGE_SMEM_F * 4>>>(ei, eattr, eb2, cW1, cb1,
                                                     cW2, cb2, l);
        node_kernel<<<ngrid, TPB, NODE_SMEM_F * 4>>>(nW1, nb1, nW2, nb2, l);
    }
    final_kernel<<<(N_NODES * 32 + 255) / 256, 256>>>(linW, linb, out);
}

// round 15
// speedup vs baseline: 1.0031x; 1.0031x over previous
#include <cuda_runtime.h>
#include <math.h>

#define N_NODES 50000
#define N_EDGES 400000
#define HID 64
#define F_IN 8
#define NL 3

// padded dims
#define K1 132    // e_in padded (130 -> 132)
#define N1 288    // edge hidden padded (260 -> 288)
#define K2 260    // GEMM2 true K (eW2 used unpadded)
#define NPAD 50048

#define ETILE 48  // edges per block
#define TPB 256

// ---------------- device scratch (no allocations allowed) ----------------
__device__ float g_feats[N_NODES * HID];
__device__ float g_coors[N_NODES * 3];
__device__ float g_magg[N_NODES * HID];
__device__ float g_cdelta[N_NODES * 3];
__device__ float g_eW1p[NL * K1 * N1];
__device__ float g_eb1p[NL * N1];
__device__ float g_PA[NPAD * N1];   // feats @ W1a + b1 (per current layer)
__device__ float g_PB[NPAD * N1];   // feats @ W1b
__device__ float g_zbias[N1];       // stays zero (device globals zero-init)

__device__ __forceinline__ float silu_f(float v) {
    return v * __fdividef(1.0f, 1.0f + __expf(-v));
}

// packed f32x2 helpers (sm_103a FFMA2 path — only reachable via PTX)
typedef unsigned long long u64;
__device__ __forceinline__ u64 packdup(float x) {
    u64 r;
    asm("mov.b64 %0, {%1, %1};" : "=l"(r) : "r"(__float_as_uint(x)));
    return r;
}
__device__ __forceinline__ float2 unpackf2(u64 v) {
    unsigned int lo, hi;
    asm("mov.b64 {%0, %1}, %2;" : "=r"(lo), "=r"(hi) : "l"(v));
    return make_float2(__uint_as_float(lo), __uint_as_float(hi));
}
#define FFMA2(acc, a, w) \
    asm("fma.rn.f32x2 %0, %1, %2, %0;" : "+l"(acc) : "l"(a), "l"(w))

// cp.async 16B helpers (LDGSTS — register-free weight staging)
__device__ __forceinline__ void cp16(float* dst_smem, const float* src) {
    unsigned int a = (unsigned int)__cvta_generic_to_shared(dst_smem);
    asm volatile("cp.async.cg.shared.global [%0], [%1], 16;" :: "r"(a), "l"(src));
}
#define CP_COMMIT() asm volatile("cp.async.commit_group;" ::: "memory")
#define CP_WAIT0()  asm volatile("cp.async.wait_group 0;" ::: "memory")

// ---------------- GEMM tile, TPBT threads, RPT rows/thread ----------------
// C[(TPBT/32)*RPT][N] = act(A @ Wg + Bg)
// Thread (er=tid>>5, cc=tid&31): rows er*RPT..er*RPT+RPT-1.
// Cols: pair p -> (2cc+64p, 2cc+64p+1), p<P; scalar col 64P+cc if R==1.
// Wg staged via cp.async into Wst (double-buffered, KC rows/chunk, KC%4==0).
// Inner loop: A read float4-per-quad into a4[RPT] registers; W register
// double-buffered one k ahead (wc/wn) so the LDS latency overlaps the FMAs
// of the previous k instead of serializing with them.
template<int K, int N, int KC, int AS, int CS, int P, int R, bool ACT, int RPT,
         int TPBT>
__device__ __forceinline__ void gemm_tile(const float* __restrict__ A,
                                          const float* __restrict__ Wg,
                                          const float* __restrict__ Bg,
                                          float* __restrict__ C,
                                          float* __restrict__ Wst)
{
    static_assert(KC % 4 == 0, "KC must be a multiple of 4");
    constexpr int NCHUNK = K / KC;
    constexpr int CHSZ = KC * N;
    constexpr int NLD = CHSZ / 4;     // 16B transfers per chunk
    const int tid = threadIdx.x;
    const int er = tid >> 5;
    const int cc = tid & 31;

    u64 accp[RPT][P];
    float accs[RPT];
#pragma unroll
    for (int i = 0; i < RPT; i++) {
        accs[i] = 0.0f;
#pragma unroll
        for (int p = 0; p < P; p++) accp[i][p] = 0ULL;
    }

    // preload chunk 0 into buffer 0
    for (int i = tid; i < NLD; i += TPBT) cp16(Wst + 4 * i, Wg + 4 * i);
    CP_COMMIT();
    CP_WAIT0();
    __syncthreads();

    for (int c = 0; c < NCHUNK; c++) {
        const float* buf = Wst + (c & 1) * CHSZ;
        float* nbuf = Wst + ((c + 1) & 1) * CHSZ;
        if (c + 1 < NCHUNK) {
            const float* src = Wg + (c + 1) * CHSZ;
            for (int i = tid; i < NLD; i += TPBT) cp16(nbuf + 4 * i, src + 4 * i);
            CP_COMMIT();
        }
        const int k0 = c * KC;

        // W register double-buffer, primed with local k=0
        u64 wc[P], wn[P];
        float wsc = 0.0f, wsn = 0.0f;
#pragma unroll
        for (int p = 0; p < P; p++) wc[p] = *(const u64*)(buf + 2 * cc + 64 * p);
        if (R) wsc = buf[64 * P + cc];

#pragma unroll
        for (int kk = 0; kk < KC; kk += 4) {
            // A quad per row (held across the 4 inner k's)
            float4 a4[RPT];
#pragma unroll
            for (int i = 0; i < RPT; i++)
                a4[i] = *(const float4*)(A + (er * RPT + i) * AS + k0 + kk);
#pragma unroll
            for (int k = 0; k < 4; k++) {
                const int kn = kk + k + 1;
                if (kn < KC) {
#pragma unroll
                    for (int p = 0; p < P; p++)
                        wn[p] = *(const u64*)(buf + kn * N + 2 * cc + 64 * p);
                    if (R) wsn = buf[kn * N + 64 * P + cc];
                }
#pragma unroll
                for (int i = 0; i < RPT; i++) {
                    float av = (k == 0) ? a4[i].x : (k == 1) ? a4[i].y
                             : (k == 2) ? a4[i].z : a4[i].w;
                    u64 ad = packdup(av);
#pragma unroll
                    for (int p = 0; p < P; p++) FFMA2(accp[i][p], ad, wc[p]);
                    if (R) accs[i] = fmaf(av, wsc, accs[i]);
                }
#pragma unroll
                for (int p = 0; p < P; p++) wc[p] = wn[p];
                if (R) wsc = wsn;
            }
        }
        if (c + 1 < NCHUNK) CP_WAIT0();
        __syncthreads();
    }

    // epilogue: bias + activation + store
    float2 bv[P];
    float bs = 0.0f;
#pragma unroll
    for (int p = 0; p < P; p++) bv[p] = *(const float2*)(Bg + 2 * cc + 64 * p);
    if (R) bs = Bg[64 * P + cc];
#pragma unroll
    for (int i = 0; i < RPT; i++) {
#pragma unroll
        for (int p = 0; p < P; p++) {
            float2 v = unpackf2(accp[i][p]);
            v.x += bv[p].x;
            v.y += bv[p].y;
            if (ACT) { v.x = silu_f(v.x); v.y = silu_f(v.y); }
            *(float2*)(C + (er * RPT + i) * CS + 2 * cc + 64 * p) = v;
        }
        if (R) {
            float v = accs[i] + bs;
            if (ACT) v = silu_f(v);
            C[(er * RPT + i) * CS + 64 * P + cc] = v;
        }
    }
}

// ---------------- GEMM + fused dot tile ----------------
// cw[row] = sum_col silu(A@Wg + Bg)[row][col] * sdot[col]
// Same k-pipelined W double-buffer as gemm_tile.
template<int K, int N, int KC, int AS, int P, int RPT, int TPBT>
__device__ __forceinline__ void gemm_dot_tile(const float* __restrict__ A,
                                              const float* __restrict__ Wg,
                                              const float* __restrict__ Bg,
                                              const float* __restrict__ sdot,
                                              float* __restrict__ cwout,
                                              float* __restrict__ Wst)
{
    static_assert(KC % 4 == 0, "KC must be a multiple of 4");
    constexpr int NCHUNK = K / KC;
    constexpr int CHSZ = KC * N;
    constexpr int NLD = CHSZ / 4;
    const int tid = threadIdx.x;
    const int er = tid >> 5;
    const int cc = tid & 31;

    u64 accp[RPT][P];
#pragma unroll
    for (int i = 0; i < RPT; i++)
#pragma unroll
        for (int p = 0; p < P; p++) accp[i][p] = 0ULL;

    for (int i = tid; i < NLD; i += TPBT) cp16(Wst + 4 * i, Wg + 4 * i);
    CP_COMMIT();
    CP_WAIT0();
    __syncthreads();

    for (int c = 0; c < NCHUNK; c++) {
        const float* buf = Wst + (c & 1) * CHSZ;
        float* nbuf = Wst + ((c + 1) & 1) * CHSZ;
        if (c + 1 < NCHUNK) {
            const float* src = Wg + (c + 1) * CHSZ;
            for (int i = tid; i < NLD; i += TPBT) cp16(nbuf + 4 * i, src + 4 * i);
            CP_COMMIT();
        }
        const int k0 = c * KC;

        u64 wc[P], wn[P];
#pragma unroll
        for (int p = 0; p < P; p++) wc[p] = *(const u64*)(buf + 2 * cc + 64 * p);

#pragma unroll
        for (int kk = 0; kk < KC; kk += 4) {
            float4 a4[RPT];
#pragma unroll
            for (int i = 0; i < RPT; i++)
                a4[i] = *(const float4*)(A + (er * RPT + i) * AS + k0 + kk);
#pragma unroll
            for (int k = 0; k < 4; k++) {
                const int kn = kk + k + 1;
                if (kn < KC) {
#pragma unroll
                    for (int p = 0; p < P; p++)
                        wn[p] = *(const u64*)(buf + kn * N + 2 * cc + 64 * p);
                }
#pragma unroll
                for (int i = 0; i < RPT; i++) {
                    float av = (k == 0) ? a4[i].x : (k == 1) ? a4[i].y
                             : (k == 2) ? a4[i].z : a4[i].w;
                    u64 ad = packdup(av);
#pragma unroll
                    for (int p = 0; p < P; p++) FFMA2(accp[i][p], ad, wc[p]);
                }
#pragma unroll
                for (int p = 0; p < P; p++) wc[p] = wn[p];
            }
        }
        if (c + 1 < NCHUNK) CP_WAIT0();
        __syncthreads();
    }

    // epilogue: bias + silu + dot + warp reduce
    float2 bv[P], dv[P];
#pragma unroll
    for (int p = 0; p < P; p++) {
        bv[p] = *(const float2*)(Bg + 2 * cc + 64 * p);
        dv[p] = *(const float2*)(sdot + 2 * cc + 64 * p);
    }
#pragma unroll
    for (int i = 0; i < RPT; i++) {
        float s = 0.0f;
#pragma unroll
        for (int p = 0; p < P; p++) {
            float2 v = unpackf2(accp[i][p]);
            s += silu_f(v.x + bv[p].x) * dv[p].x;
            s += silu_f(v.y + bv[p].y) * dv[p].y;
        }
#pragma unroll
        for (int o = 16; o > 0; o >>= 1) s += __shfl_xor_sync(0xFFFFFFFFu, s, o);
        if (cc == 0) cwout[er * RPT + i] = s;
    }
}

// ---------------- weight padding / prep (eW1 only) ----------------
__global__ void __launch_bounds__(256) pad_kernel(const float* __restrict__ eW1,
                                                  const float* __restrict__ eb1)
{
    const int A = NL * K1 * N1;
    const int B = NL * N1;
    int i = blockIdx.x * 256 + threadIdx.x;
    if (i < A) {
        int l = i / (K1 * N1);
        int r = (i / N1) % K1;
        int j = i % N1;
        g_eW1p[i] = (r < 130 && j < 260) ? eW1[(l * 130 + r) * 260 + j] : 0.0f;
    } else if (i < A + B) {
        int ii = i - A;
        int l = ii / N1, j = ii % N1;
        g_eb1p[ii] = (j < 260) ? eb1[l * 260 + j] : 0.0f;
    }
}

// ---------------- embed + pos copy ----------------
__global__ void __launch_bounds__(256) embed_kernel(const float* __restrict__ x,
                                                    const float* __restrict__ pos,
                                                    const float* __restrict__ W,
                                                    const float* __restrict__ b)
{
    int idx = blockIdx.x * 256 + threadIdx.x;
    if (idx < N_NODES * 3) g_coors[idx] = pos[idx];
    if (idx < N_NODES * HID) {
        int n = idx >> 6, j = idx & 63;
        float acc = b[j];
#pragma unroll
        for (int k = 0; k < F_IN; k++) acc = fmaf(x[n * F_IN + k], W[k * HID + j], acc);
        g_feats[idx] = acc;
    }
}

// ---------------- per-node precompute (+ zero of agg buffers) ----------------
// PA = feats@W1a + b1, PB = feats@W1b; also zeroes magg/cdelta for this slice.
// smem: sF [0,4096), Wst [4096,13312)  (2 x 4608)
#define PRE_SMEM_F 13312

__global__ void __launch_bounds__(256, 2) prenode_kernel(int l)
{
    extern __shared__ float sm[];
    float* sF = sm;
    float* Wst = sm + 4096;

    const int tid = threadIdx.x;
    const int n0 = blockIdx.x * 64;

    for (int idx = tid; idx < 64 * 64; idx += TPB) {
        int nl = idx >> 6, k = idx & 63;
        int n = n0 + nl;
        float f = 0.0f;
        if (n < N_NODES) {
            f = g_feats[n * HID + k];
            g_magg[n * HID + k] = 0.0f;   // fused zeroing (pre-edge, same stream)
        }
        sF[idx] = f;
    }
    if (tid < 192) {
        int n = n0 + tid / 3;
        int d = tid % 3;
        if (n < N_NODES) g_cdelta[n * 3 + d] = 0.0f;
    }

    const float* W1 = g_eW1p + l * K1 * N1;
    gemm_tile<64, N1, 16, 64, N1, 4, 1, false, 8, TPB>(sF, W1, g_eb1p + l * N1,
                                                       g_PA + n0 * N1, Wst);
    gemm_tile<64, N1, 16, 64, N1, 4, 1, false, 8, TPB>(sF, W1 + 64 * N1, g_zbias,
                                                       g_PB + n0 * N1, Wst);
}

// ---------------- edge kernel (48 edges/block, 256 threads, 2 CTA/SM) -----
// smem float layout:
//   R1    [0, 13824)      : h1 (48x288, cols 260..287 unused)
//   mT    [13824, 16896)  : m (48x64)
//   Wst   [16896, 25088)  : double-buffered weight staging (2 x 4096)
//   sWea  [25088, 25376)  : eW1 row 128 (288)
//   sWdist[25376, 25664)  : eW1 row 129 (288)
//   scw   [25664, 25712)  : fused dot output (48)
//   srow  [25712, 25760)  : int
//   scol  [25760, 25808)  : int
//   srel  [25808, 26000)  : rx,ry,rz,dist per edge
//   sea   [26000, 26048)  : edge_attr
//   sdot  [26048, 26304)  : cW2 (256)
#define EDGE_SMEM_F 26304

__global__ void __launch_bounds__(256, 2) edge_kernel(const int* __restrict__ ei,
                                                      const float* __restrict__ eattr,
                                                      const float* __restrict__ eW2,
                                                      const float* __restrict__ eb2,
                                                      const float* __restrict__ cW1,
                                                      const float* __restrict__ cb1,
                                                      const float* __restrict__ cW2,
                                                      const float* __restrict__ cb2,
                                                      int l)
{
    extern __shared__ float sm[];
    float* R1 = sm;
    float* mT = sm + 13824;
    float* Wst = sm + 16896;
    float* sWea = sm + 25088;
    float* sWdist = sm + 25376;
    float* scw = sm + 25664;
    int* srow = (int*)(sm + 25712);
    int* scol = (int*)(sm + 25760);
    float* srel = sm + 25808;
    float* sea = sm + 26000;
    float* sdot = sm + 26048;

    const int tid = threadIdx.x;
    const int e0 = blockIdx.x * ETILE;

    // phase 0a: scalars + small weight vectors
    sdot[tid] = cW2[l * 256 + tid];
    {
        const float* Wea = g_eW1p + l * K1 * N1 + 128 * N1;
        for (int idx = tid; idx < 2 * N1; idx += TPB) {
            if (idx < N1) sWea[idx] = Wea[idx];
            else sWdist[idx - N1] = Wea[N1 + (idx - N1)];
        }
    }
    if (tid < ETILE) {
        int e = e0 + tid;
        int r = 0, c = 0;
        float ea = 0.0f;
        if (e < N_EDGES) {
            r = ei[e];
            c = ei[N_EDGES + e];
            ea = eattr[e];
        }
        srow[tid] = r;
        scol[tid] = c;
        float rx = g_coors[r * 3 + 0] - g_coors[c * 3 + 0];
        float ry = g_coors[r * 3 + 1] - g_coors[c * 3 + 1];
        float rz = g_coors[r * 3 + 2] - g_coors[c * 3 + 2];
        srel[tid * 4 + 0] = rx;
        srel[tid * 4 + 1] = ry;
        srel[tid * 4 + 2] = rz;
        srel[tid * 4 + 3] = rx * rx + ry * ry + rz * rz;
        sea[tid] = ea;
    }
    __syncthreads();

    // phase A: h1[e][0:260] = silu(PA[row] + PB[col] + ea*Wea + dist*Wdist)
    // (cols 260..287 never read by GEMM2 since K2=260)
    for (int idx = tid; idx < ETILE * 65; idx += TPB) {
        int e = idx / 65, q = idx - e * 65;
        float4 a = ((const float4*)(g_PA + srow[e] * N1))[q];
        float4 b = ((const float4*)(g_PB + scol[e] * N1))[q];
        float4 we = ((const float4*)sWea)[q];
        float4 wd = ((const float4*)sWdist)[q];
        float ea = sea[e], di = srel[e * 4 + 3];
        float4 v;
        v.x = silu_f(fmaf(di, wd.x, fmaf(ea, we.x, a.x + b.x)));
        v.y = silu_f(fmaf(di, wd.y, fmaf(ea, we.y, a.y + b.y)));
        v.z = silu_f(fmaf(di, wd.z, fmaf(ea, we.z, a.z + b.z)));
        v.w = silu_f(fmaf(di, wd.w, fmaf(ea, we.w, a.w + b.w)));
        ((float4*)(R1 + e * N1))[q] = v;
    }

    // GEMM2: m = silu(h1[:, :260] @ eW2 + eb2)   (preload sync covers phase A)
    gemm_tile<K2, 64, 52, N1, 64, 1, 0, true, 6, TPB>(R1, eW2 + l * K2 * HID,
                                                      eb2 + l * HID, mT, Wst);
    // GEMM3 + dot fused: scw[e] = silu(m @ cW1 + cb1) . cW2
    gemm_dot_tile<64, 256, 16, 64, 4, 6, TPB>(mT, cW1 + l * 64 * 256,
                                              cb1 + l * 256, sdot, scw, Wst);
    __syncthreads();

    // coords atomics
    if (tid < ETILE) {
        int e = tid;
        if (e0 + e < N_EDGES) {
            float cw = scw[e] + cb2[l];
            int r = srow[e];
            atomicAdd(&g_cdelta[r * 3 + 0], cw * srel[e * 4 + 0]);
            atomicAdd(&g_cdelta[r * 3 + 1], cw * srel[e * 4 + 1]);
            atomicAdd(&g_cdelta[r * 3 + 2], cw * srel[e * 4 + 2]);
        }
    }
    // scatter m into node aggregation
    for (int idx = tid; idx < ETILE * 64; idx += TPB) {
        int e = idx >> 6, k = idx & 63;
        if (e0 + e < N_EDGES)
            atomicAdd(&g_magg[srow[e] * HID + k], mT[e * 64 + k]);
    }
}

// ---------------- node kernel (64 nodes/block, 256 threads) ----------------
// smem: sH [0,8192), sT1 [8192,16384), Wst [16384,24576)  (2 x 4096)
#define NODE_SMEM_F 24576

__global__ void __launch_bounds__(256, 2) node_kernel(const float* __restrict__ nW1,
                                                      const float* __restrict__ nb1,
                                                      const float* __restrict__ nW2,
                                                      const float* __restrict__ nb2,
                                                      int l)
{
    extern __shared__ float sm[];
    float* sH = sm;
    float* sT1 = sm + 8192;
    float* Wst = sm + 16384;

    const int tid = threadIdx.x;
    const int n0 = blockIdx.x * 64;

    for (int idx = tid; idx < 64 * 64; idx += TPB) {
        int nl = idx >> 6, k = idx & 63;
        int n = n0 + nl;
        float f = 0.0f, mg = 0.0f;
        if (n < N_NODES) { f = g_feats[n * HID + k]; mg = g_magg[n * HID + k]; }
        sH[nl * 128 + k] = f;
        sH[nl * 128 + 64 + k] = mg;
    }

    gemm_tile<128, 128, 32, 128, 128, 2, 0, true, 8, TPB>(sH, nW1 + l * 128 * 128,
                                                          nb1 + l * 128, sT1, Wst);
    gemm_tile<128, 64, 32, 128, 64, 1, 0, false, 8, TPB>(sT1, nW2 + l * 128 * 64,
                                                         nb2 + l * 64, sH, Wst);
    __syncthreads();

    for (int idx = tid; idx < 64 * 64; idx += TPB) {
        int nl = idx >> 6, k = idx & 63;
        int n = n0 + nl;
        if (n < N_NODES) g_feats[n * HID + k] += sH[idx];
    }
    if (tid < 192) {
        int n = n0 + tid / 3;
        int d = tid % 3;
        if (n < N_NODES) g_coors[n * 3 + d] += g_cdelta[n * 3 + d];
    }
}

// ---------------- final projection ----------------
__global__ void __launch_bounds__(256) final_kernel(const float* __restrict__ linW,
                                                    const float* __restrict__ linb,
                                                    float* __restrict__ out)
{
    int warp = (blockIdx.x * 256 + threadIdx.x) >> 5;
    int lane = threadIdx.x & 31;
    if (warp >= N_NODES) return;
    const float* f = g_feats + warp * HID;
    float s = fmaf(f[lane], linW[lane], f[lane + 32] * linW[lane + 32]);
#pragma unroll
    for (int o = 16; o > 0; o >>= 1) s += __shfl_xor_sync(0xFFFFFFFFu, s, o);
    if (lane == 0) out[warp] = s + linb[0];
}

// ---------------- launch ----------------
extern "C" void kernel_launch(void* const* d_in, const int* in_sizes, int n_in,
                              void* d_out, int out_size)
{
    const float* x      = (const float*)d_in[0];
    const float* pos    = (const float*)d_in[1];
    const int*   ei     = (const int*)  d_in[2];
    const float* eattr  = (const float*)d_in[3];
    const float* embedW = (const float*)d_in[4];
    const float* embedb = (const float*)d_in[5];
    const float* eW1    = (const float*)d_in[6];
    const float* eb1    = (const float*)d_in[7];
    const float* eW2    = (const float*)d_in[8];
    const float* eb2    = (const float*)d_in[9];
    const float* cW1    = (const float*)d_in[10];
    const float* cb1    = (const float*)d_in[11];
    const float* cW2    = (const float*)d_in[12];
    const float* cb2    = (const float*)d_in[13];
    const float* nW1    = (const float*)d_in[14];
    const float* nb1    = (const float*)d_in[15];
    const float* nW2    = (const float*)d_in[16];
    const float* nb2    = (const float*)d_in[17];
    const float* linW   = (const float*)d_in[18];
    const float* linb   = (const float*)d_in[19];
    float* out = (float*)d_out;

    cudaFuncSetAttribute(edge_kernel, cudaFuncAttributeMaxDynamicSharedMemorySize,
                         EDGE_SMEM_F * 4);
    cudaFuncSetAttribute(node_kernel, cudaFuncAttributeMaxDynamicSharedMemorySize,
                         NODE_SMEM_F * 4);
    cudaFuncSetAttribute(prenode_kernel, cudaFuncAttributeMaxDynamicSharedMemorySize,
                         PRE_SMEM_F * 4);

    {
        int total = NL * K1 * N1 + NL * N1;
        pad_kernel<<<(total + 255) / 256, 256>>>(eW1, eb1);
    }
    embed_kernel<<<(N_NODES * HID + 255) / 256, 256>>>(x, pos, embedW, embedb);

    const int egrid = (N_EDGES + ETILE - 1) / ETILE;
    const int ngrid = (N_NODES + 63) / 64;
    for (int l = 0; l < NL; l++) {
        prenode_kernel<<<ngrid, TPB, PRE_SMEM_F * 4>>>(l);
        edge_kernel<<<egrid, TPB, EDGE_SMEM_F * 4>>>(ei, eattr, eW2, eb2, cW1, cb1,
                                                     cW2, cb2, l);
        node_kernel<<<ngrid, TPB, NODE_SMEM_F * 4>>>(nW1, nb1, nW2, nb2, l);
    }
    final_kernel<<<(N_NODES * 32 + 255) / 256, 256>>>(linW, linb, out);
}

// round 17
// speedup vs baseline: 1.0105x; 1.0074x over previous
#include <cuda_runtime.h>
#include <math.h>

#define N_NODES 50000
#define N_EDGES 400000
#define HID 64
#define F_IN 8
#define NL 3

// padded dims
#define K1 132    // e_in padded (130 -> 132)
#define N1 288    // edge hidden padded (260 -> 288)
#define K2 260    // GEMM2 true K (eW2 used unpadded)
#define NPAD 50048

#define ETILE 48  // edges per block
#define TPB 256

// ---------------- device scratch (no allocations allowed) ----------------
__device__ float g_feats[N_NODES * HID];
__device__ float g_coors[N_NODES * 3];
__device__ float g_magg[N_NODES * HID];
__device__ float g_cdelta[N_NODES * 3];
__device__ float g_eW1p[NL * K1 * N1];
__device__ float g_eb1p[NL * N1];
__device__ float g_PA[NPAD * N1];   // feats @ W1a + b1 (per current layer)
__device__ float g_PB[NPAD * N1];   // feats @ W1b
__device__ float g_zbias[N1];       // stays zero (device globals zero-init)

__device__ __forceinline__ float silu_f(float v) {
    return v * __fdividef(1.0f, 1.0f + __expf(-v));
}

// packed f32x2 helpers (sm_103a FFMA2 path — only reachable via PTX)
typedef unsigned long long u64;
__device__ __forceinline__ u64 packdup(float x) {
    u64 r;
    asm("mov.b64 %0, {%1, %1};" : "=l"(r) : "r"(__float_as_uint(x)));
    return r;
}
__device__ __forceinline__ float2 unpackf2(u64 v) {
    unsigned int lo, hi;
    asm("mov.b64 {%0, %1}, %2;" : "=r"(lo), "=r"(hi) : "l"(v));
    return make_float2(__uint_as_float(lo), __uint_as_float(hi));
}
#define FFMA2(acc, a, w) \
    asm("fma.rn.f32x2 %0, %1, %2, %0;" : "+l"(acc) : "l"(a), "l"(w))

// cp.async 16B helpers (LDGSTS — register-free weight staging)
__device__ __forceinline__ void cp16(float* dst_smem, const float* src) {
    unsigned int a = (unsigned int)__cvta_generic_to_shared(dst_smem);
    asm volatile("cp.async.cg.shared.global [%0], [%1], 16;" :: "r"(a), "l"(src));
}
#define CP_COMMIT() asm volatile("cp.async.commit_group;" ::: "memory")
#define CP_WAIT0()  asm volatile("cp.async.wait_group 0;" ::: "memory")

// ---------------- GEMM tile, TPBT threads, RPT rows/thread ----------------
// C[(TPBT/32)*RPT][N] = act(A @ Wg + Bg)
// Thread (er=tid>>5, cc=tid&31): rows er*RPT..er*RPT+RPT-1.
// Cols: pair p -> (2cc+64p, 2cc+64p+1), p<P; scalar col 64P+cc if R==1.
// Wg staged via cp.async into Wst (double-buffered, KC rows/chunk, KC%4==0).
// Inner loop: A read float4-per-quad into a4[RPT] registers; W register
// double-buffered one k ahead (wc/wn) so the LDS latency overlaps the FMAs
// of the previous k instead of serializing with them.
template<int K, int N, int KC, int AS, int CS, int P, int R, bool ACT, int RPT,
         int TPBT>
__device__ __forceinline__ void gemm_tile(const float* __restrict__ A,
                                          const float* __restrict__ Wg,
                                          const float* __restrict__ Bg,
                                          float* __restrict__ C,
                                          float* __restrict__ Wst)
{
    static_assert(KC % 4 == 0, "KC must be a multiple of 4");
    constexpr int NCHUNK = K / KC;
    constexpr int CHSZ = KC * N;
    constexpr int NLD = CHSZ / 4;     // 16B transfers per chunk
    const int tid = threadIdx.x;
    const int er = tid >> 5;
    const int cc = tid & 31;

    u64 accp[RPT][P];
    float accs[RPT];
#pragma unroll
    for (int i = 0; i < RPT; i++) {
        accs[i] = 0.0f;
#pragma unroll
        for (int p = 0; p < P; p++) accp[i][p] = 0ULL;
    }

    // preload chunk 0 into buffer 0
    for (int i = tid; i < NLD; i += TPBT) cp16(Wst + 4 * i, Wg + 4 * i);
    CP_COMMIT();
    CP_WAIT0();
    __syncthreads();

    for (int c = 0; c < NCHUNK; c++) {
        const float* buf = Wst + (c & 1) * CHSZ;
        float* nbuf = Wst + ((c + 1) & 1) * CHSZ;
        if (c + 1 < NCHUNK) {
            const float* src = Wg + (c + 1) * CHSZ;
            for (int i = tid; i < NLD; i += TPBT) cp16(nbuf + 4 * i, src + 4 * i);
            CP_COMMIT();
        }
        const int k0 = c * KC;

        // W register double-buffer, primed with local k=0
        u64 wc[P], wn[P];
        float wsc = 0.0f, wsn = 0.0f;
#pragma unroll
        for (int p = 0; p < P; p++) wc[p] = *(const u64*)(buf + 2 * cc + 64 * p);
        if (R) wsc = buf[64 * P + cc];

#pragma unroll
        for (int kk = 0; kk < KC; kk += 4) {
            // A quad per row (held across the 4 inner k's)
            float4 a4[RPT];
#pragma unroll
            for (int i = 0; i < RPT; i++)
                a4[i] = *(const float4*)(A + (er * RPT + i) * AS + k0 + kk);
#pragma unroll
            for (int k = 0; k < 4; k++) {
                const int kn = kk + k + 1;
                if (kn < KC) {
#pragma unroll
                    for (int p = 0; p < P; p++)
                        wn[p] = *(const u64*)(buf + kn * N + 2 * cc + 64 * p);
                    if (R) wsn = buf[kn * N + 64 * P + cc];
                }
#pragma unroll
                for (int i = 0; i < RPT; i++) {
                    float av = (k == 0) ? a4[i].x : (k == 1) ? a4[i].y
                             : (k == 2) ? a4[i].z : a4[i].w;
                    u64 ad = packdup(av);
#pragma unroll
                    for (int p = 0; p < P; p++) FFMA2(accp[i][p], ad, wc[p]);
                    if (R) accs[i] = fmaf(av, wsc, accs[i]);
                }
#pragma unroll
                for (int p = 0; p < P; p++) wc[p] = wn[p];
                if (R) wsc = wsn;
            }
        }
        if (c + 1 < NCHUNK) CP_WAIT0();
        __syncthreads();
    }

    // epilogue: bias + activation + store
    float2 bv[P];
    float bs = 0.0f;
#pragma unroll
    for (int p = 0; p < P; p++) bv[p] = *(const float2*)(Bg + 2 * cc + 64 * p);
    if (R) bs = Bg[64 * P + cc];
#pragma unroll
    for (int i = 0; i < RPT; i++) {
#pragma unroll
        for (int p = 0; p < P; p++) {
            float2 v = unpackf2(accp[i][p]);
            v.x += bv[p].x;
            v.y += bv[p].y;
            if (ACT) { v.x = silu_f(v.x); v.y = silu_f(v.y); }
            *(float2*)(C + (er * RPT + i) * CS + 2 * cc + 64 * p) = v;
        }
        if (R) {
            float v = accs[i] + bs;
            if (ACT) v = silu_f(v);
            C[(er * RPT + i) * CS + 64 * P + cc] = v;
        }
    }
}

// ---------------- GEMM + fused dot tile ----------------
// cw[row] = sum_col silu(A@Wg + Bg)[row][col] * sdot[col]
// Same k-pipelined W double-buffer as gemm_tile.
template<int K, int N, int KC, int AS, int P, int RPT, int TPBT>
__device__ __forceinline__ void gemm_dot_tile(const float* __restrict__ A,
                                              const float* __restrict__ Wg,
                                              const float* __restrict__ Bg,
                                              const float* __restrict__ sdot,
                                              float* __restrict__ cwout,
                                              float* __restrict__ Wst)
{
    static_assert(KC % 4 == 0, "KC must be a multiple of 4");
    constexpr int NCHUNK = K / KC;
    constexpr int CHSZ = KC * N;
    constexpr int NLD = CHSZ / 4;
    const int tid = threadIdx.x;
    const int er = tid >> 5;
    const int cc = tid & 31;

    u64 accp[RPT][P];
#pragma unroll
    for (int i = 0; i < RPT; i++)
#pragma unroll
        for (int p = 0; p < P; p++) accp[i][p] = 0ULL;

    for (int i = tid; i < NLD; i += TPBT) cp16(Wst + 4 * i, Wg + 4 * i);
    CP_COMMIT();
    CP_WAIT0();
    __syncthreads();

    for (int c = 0; c < NCHUNK; c++) {
        const float* buf = Wst + (c & 1) * CHSZ;
        float* nbuf = Wst + ((c + 1) & 1) * CHSZ;
        if (c + 1 < NCHUNK) {
            const float* src = Wg + (c + 1) * CHSZ;
            for (int i = tid; i < NLD; i += TPBT) cp16(nbuf + 4 * i, src + 4 * i);
            CP_COMMIT();
        }
        const int k0 = c * KC;

        u64 wc[P], wn[P];
#pragma unroll
        for (int p = 0; p < P; p++) wc[p] = *(const u64*)(buf + 2 * cc + 64 * p);

#pragma unroll
        for (int kk = 0; kk < KC; kk += 4) {
            float4 a4[RPT];
#pragma unroll
            for (int i = 0; i < RPT; i++)
                a4[i] = *(const float4*)(A + (er * RPT + i) * AS + k0 + kk);
#pragma unroll
            for (int k = 0; k < 4; k++) {
                const int kn = kk + k + 1;
                if (kn < KC) {
#pragma unroll
                    for (int p = 0; p < P; p++)
                        wn[p] = *(const u64*)(buf + kn * N + 2 * cc + 64 * p);
                }
#pragma unroll
                for (int i = 0; i < RPT; i++) {
                    float av = (k == 0) ? a4[i].x : (k == 1) ? a4[i].y
                             : (k == 2) ? a4[i].z : a4[i].w;
                    u64 ad = packdup(av);
#pragma unroll
                    for (int p = 0; p < P; p++) FFMA2(accp[i][p], ad, wc[p]);
                }
#pragma unroll
                for (int p = 0; p < P; p++) wc[p] = wn[p];
            }
        }
        if (c + 1 < NCHUNK) CP_WAIT0();
        __syncthreads();
    }

    // epilogue: bias + silu + dot + warp reduce
    float2 bv[P], dv[P];
#pragma unroll
    for (int p = 0; p < P; p++) {
        bv[p] = *(const float2*)(Bg + 2 * cc + 64 * p);
        dv[p] = *(const float2*)(sdot + 2 * cc + 64 * p);
    }
#pragma unroll
    for (int i = 0; i < RPT; i++) {
        float s = 0.0f;
#pragma unroll
        for (int p = 0; p < P; p++) {
            float2 v = unpackf2(accp[i][p]);
            s += silu_f(v.x + bv[p].x) * dv[p].x;
            s += silu_f(v.y + bv[p].y) * dv[p].y;
        }
#pragma unroll
        for (int o = 16; o > 0; o >>= 1) s += __shfl_xor_sync(0xFFFFFFFFu, s, o);
        if (cc == 0) cwout[er * RPT + i] = s;
    }
}

// ---------------- weight padding / prep (eW1 only) ----------------
__global__ void __launch_bounds__(256) pad_kernel(const float* __restrict__ eW1,
                                                  const float* __restrict__ eb1)
{
    const int A = NL * K1 * N1;
    const int B = NL * N1;
    int i = blockIdx.x * 256 + threadIdx.x;
    if (i < A) {
        int l = i / (K1 * N1);
        int r = (i / N1) % K1;
        int j = i % N1;
        g_eW1p[i] = (r < 130 && j < 260) ? eW1[(l * 130 + r) * 260 + j] : 0.0f;
    } else if (i < A + B) {
        int ii = i - A;
        int l = ii / N1, j = ii % N1;
        g_eb1p[ii] = (j < 260) ? eb1[l * 260 + j] : 0.0f;
    }
}

// ---------------- embed + pos copy ----------------
__global__ void __launch_bounds__(256) embed_kernel(const float* __restrict__ x,
                                                    const float* __restrict__ pos,
                                                    const float* __restrict__ W,
                                                    const float* __restrict__ b)
{
    int idx = blockIdx.x * 256 + threadIdx.x;
    if (idx < N_NODES * 3) g_coors[idx] = pos[idx];
    if (idx < N_NODES * HID) {
        int n = idx >> 6, j = idx & 63;
        float acc = b[j];
#pragma unroll
        for (int k = 0; k < F_IN; k++) acc = fmaf(x[n * F_IN + k], W[k * HID + j], acc);
        g_feats[idx] = acc;
    }
}

// ---------------- per-node precompute (+ zero of agg buffers) ----------------
// PA = feats@W1a + b1, PB = feats@W1b; also zeroes magg/cdelta for this slice.
// smem: sF [0,4096), Wst [4096,13312)  (2 x 4608)
#define PRE_SMEM_F 13312

__global__ void __launch_bounds__(256, 2) prenode_kernel(int l)
{
    extern __shared__ float sm[];
    float* sF = sm;
    float* Wst = sm + 4096;

    const int tid = threadIdx.x;
    const int n0 = blockIdx.x * 64;

    for (int idx = tid; idx < 64 * 64; idx += TPB) {
        int nl = idx >> 6, k = idx & 63;
        int n = n0 + nl;
        float f = 0.0f;
        if (n < N_NODES) {
            f = g_feats[n * HID + k];
            g_magg[n * HID + k] = 0.0f;   // fused zeroing (pre-edge, same stream)
        }
        sF[idx] = f;
    }
    if (tid < 192) {
        int n = n0 + tid / 3;
        int d = tid % 3;
        if (n < N_NODES) g_cdelta[n * 3 + d] = 0.0f;
    }

    const float* W1 = g_eW1p + l * K1 * N1;
    gemm_tile<64, N1, 16, 64, N1, 4, 1, false, 8, TPB>(sF, W1, g_eb1p + l * N1,
                                                       g_PA + n0 * N1, Wst);
    gemm_tile<64, N1, 16, 64, N1, 4, 1, false, 8, TPB>(sF, W1 + 64 * N1, g_zbias,
                                                       g_PB + n0 * N1, Wst);
}

// ---------------- edge kernel (48 edges/block, 256 threads, 2 CTA/SM) -----
// smem float layout:
//   R1    [0, 13824)      : h1 (48x288, cols 260..287 unused)
//   mT    [13824, 16896)  : m (48x64)
//   Wst   [16896, 25088)  : double-buffered weight staging (2 x 4096)
//   sWea  [25088, 25376)  : eW1 row 128 (288)
//   sWdist[25376, 25664)  : eW1 row 129 (288)
//   scw   [25664, 25712)  : fused dot output (48)
//   srow  [25712, 25760)  : int
//   scol  [25760, 25808)  : int
//   srel  [25808, 26000)  : rx,ry,rz,dist per edge
//   sea   [26000, 26048)  : edge_attr
//   sdot  [26048, 26304)  : cW2 (256)
#define EDGE_SMEM_F 26304

__global__ void __launch_bounds__(256, 2) edge_kernel(const int* __restrict__ ei,
                                                      const float* __restrict__ eattr,
                                                      const float* __restrict__ eW2,
                                                      const float* __restrict__ eb2,
                                                      const float* __restrict__ cW1,
                                                      const float* __restrict__ cb1,
                                                      const float* __restrict__ cW2,
                                                      const float* __restrict__ cb2,
                                                      int l)
{
    extern __shared__ float sm[];
    float* R1 = sm;
    float* mT = sm + 13824;
    float* Wst = sm + 16896;
    float* sWea = sm + 25088;
    float* sWdist = sm + 25376;
    float* scw = sm + 25664;
    int* srow = (int*)(sm + 25712);
    int* scol = (int*)(sm + 25760);
    float* srel = sm + 25808;
    float* sea = sm + 26000;
    float* sdot = sm + 26048;

    const int tid = threadIdx.x;
    const int e0 = blockIdx.x * ETILE;

    // phase 0a: scalars + small weight vectors
    sdot[tid] = cW2[l * 256 + tid];
    {
        const float* Wea = g_eW1p + l * K1 * N1 + 128 * N1;
        for (int idx = tid; idx < 2 * N1; idx += TPB) {
            if (idx < N1) sWea[idx] = Wea[idx];
            else sWdist[idx - N1] = Wea[N1 + (idx - N1)];
        }
    }
    if (tid < ETILE) {
        int e = e0 + tid;
        int r = 0, c = 0;
        float ea = 0.0f;
        if (e < N_EDGES) {
            r = ei[e];
            c = ei[N_EDGES + e];
            ea = eattr[e];
        }
        srow[tid] = r;
        scol[tid] = c;
        float rx = g_coors[r * 3 + 0] - g_coors[c * 3 + 0];
        float ry = g_coors[r * 3 + 1] - g_coors[c * 3 + 1];
        float rz = g_coors[r * 3 + 2] - g_coors[c * 3 + 2];
        srel[tid * 4 + 0] = rx;
        srel[tid * 4 + 1] = ry;
        srel[tid * 4 + 2] = rz;
        srel[tid * 4 + 3] = rx * rx + ry * ry + rz * rz;
        sea[tid] = ea;
    }
    __syncthreads();

    // phase A: h1[e][0:260] = silu(PA[row] + PB[col] + ea*Wea + dist*Wdist)
    // (cols 260..287 never read by GEMM2 since K2=260)
    for (int idx = tid; idx < ETILE * 65; idx += TPB) {
        int e = idx / 65, q = idx - e * 65;
        float4 a = ((const float4*)(g_PA + srow[e] * N1))[q];
        float4 b = ((const float4*)(g_PB + scol[e] * N1))[q];
        float4 we = ((const float4*)sWea)[q];
        float4 wd = ((const float4*)sWdist)[q];
        float ea = sea[e], di = srel[e * 4 + 3];
        float4 v;
        v.x = silu_f(fmaf(di, wd.x, fmaf(ea, we.x, a.x + b.x)));
        v.y = silu_f(fmaf(di, wd.y, fmaf(ea, we.y, a.y + b.y)));
        v.z = silu_f(fmaf(di, wd.z, fmaf(ea, we.z, a.z + b.z)));
        v.w = silu_f(fmaf(di, wd.w, fmaf(ea, we.w, a.w + b.w)));
        ((float4*)(R1 + e * N1))[q] = v;
    }

    // GEMM2: m = silu(h1[:, :260] @ eW2 + eb2)   (preload sync covers phase A)
    gemm_tile<K2, 64, 52, N1, 64, 1, 0, true, 6, TPB>(R1, eW2 + l * K2 * HID,
                                                      eb2 + l * HID, mT, Wst);
    __syncthreads();   // order GEMM2 epilogue writes to mT vs cross-thread reads

    // scatter m into node aggregation EARLY: REDG atomics are posted
    // (no return), so their completion hides under GEMM3's compute instead
    // of sitting exposed in the kernel tail.
    for (int idx = tid; idx < ETILE * 64; idx += TPB) {
        int e = idx >> 6, k = idx & 63;
        if (e0 + e < N_EDGES)
            atomicAdd(&g_magg[srow[e] * HID + k], mT[e * 64 + k]);
    }

    // GEMM3 + dot fused: scw[e] = silu(m @ cW1 + cb1) . cW2
    gemm_dot_tile<64, 256, 16, 64, 4, 6, TPB>(mT, cW1 + l * 64 * 256,
                                              cb1 + l * 256, sdot, scw, Wst);
    __syncthreads();

    // coords atomics (depend on scw -> stay after gemm_dot)
    if (tid < ETILE) {
        int e = tid;
        if (e0 + e < N_EDGES) {
            float cw = scw[e] + cb2[l];
            int r = srow[e];
            atomicAdd(&g_cdelta[r * 3 + 0], cw * srel[e * 4 + 0]);
            atomicAdd(&g_cdelta[r * 3 + 1], cw * srel[e * 4 + 1]);
            atomicAdd(&g_cdelta[r * 3 + 2], cw * srel[e * 4 + 2]);
        }
    }
}

// ---------------- node kernel (64 nodes/block, 256 threads) ----------------
// smem: sH [0,8192), sT1 [8192,16384), Wst [16384,24576)  (2 x 4096)
#define NODE_SMEM_F 24576

__global__ void __launch_bounds__(256, 2) node_kernel(const float* __restrict__ nW1,
                                                      const float* __restrict__ nb1,
                                                      const float* __restrict__ nW2,
                                                      const float* __restrict__ nb2,
                                                      int l)
{
    extern __shared__ float sm[];
    float* sH = sm;
    float* sT1 = sm + 8192;
    float* Wst = sm + 16384;

    const int tid = threadIdx.x;
    const int n0 = blockIdx.x * 64;

    for (int idx = tid; idx < 64 * 64; idx += TPB) {
        int nl = idx >> 6, k = idx & 63;
        int n = n0 + nl;
        float f = 0.0f, mg = 0.0f;
        if (n < N_NODES) { f = g_feats[n * HID + k]; mg = g_magg[n * HID + k]; }
        sH[nl * 128 + k] = f;
        sH[nl * 128 + 64 + k] = mg;
    }

    gemm_tile<128, 128, 32, 128, 128, 2, 0, true, 8, TPB>(sH, nW1 + l * 128 * 128,
                                                          nb1 + l * 128, sT1, Wst);
    gemm_tile<128, 64, 32, 128, 64, 1, 0, false, 8, TPB>(sT1, nW2 + l * 128 * 64,
                                                         nb2 + l * 64, sH, Wst);
    __syncthreads();

    for (int idx = tid; idx < 64 * 64; idx += TPB) {
        int nl = idx >> 6, k = idx & 63;
        int n = n0 + nl;
        if (n < N_NODES) g_feats[n * HID + k] += sH[idx];
    }
    if (tid < 192) {
        int n = n0 + tid / 3;
        int d = tid % 3;
        if (n < N_NODES) g_coors[n * 3 + d] += g_cdelta[n * 3 + d];
    }
}

// ---------------- final projection ----------------
__global__ void __launch_bounds__(256) final_kernel(const float* __restrict__ linW,
                                                    const float* __restrict__ linb,
                                                    float* __restrict__ out)
{
    int warp = (blockIdx.x * 256 + threadIdx.x) >> 5;
    int lane = threadIdx.x & 31;
    if (warp >= N_NODES) return;
    const float* f = g_feats + warp * HID;
    float s = fmaf(f[lane], linW[lane], f[lane + 32] * linW[lane + 32]);
#pragma unroll
    for (int o = 16; o > 0; o >>= 1) s += __shfl_xor_sync(0xFFFFFFFFu, s, o);
    if (lane == 0) out[warp] = s + linb[0];
}

// ---------------- launch ----------------
extern "C" void kernel_launch(void* const* d_in, const int* in_sizes, int n_in,
                              void* d_out, int out_size)
{
    const float* x      = (const float*)d_in[0];
    const float* pos    = (const float*)d_in[1];
    const int*   ei     = (const int*)  d_in[2];
    const float* eattr  = (const float*)d_in[3];
    const float* embedW = (const float*)d_in[4];
    const float* embedb = (const float*)d_in[5];
    const float* eW1    = (const float*)d_in[6];
    const float* eb1    = (const float*)d_in[7];
    const float* eW2    = (const float*)d_in[8];
    const float* eb2    = (const float*)d_in[9];
    const float* cW1    = (const float*)d_in[10];
    const float* cb1    = (const float*)d_in[11];
    const float* cW2    = (const float*)d_in[12];
    const float* cb2    = (const float*)d_in[13];
    const float* nW1    = (const float*)d_in[14];
    const float* nb1    = (const float*)d_in[15];
    const float* nW2    = (const float*)d_in[16];
    const float* nb2    = (const float*)d_in[17];
    const float* linW   = (const float*)d_in[18];
    const float* linb   = (const float*)d_in[19];
    float* out = (float*)d_out;

    cudaFuncSetAttribute(edge_kernel, cudaFuncAttributeMaxDynamicSharedMemorySize,
                         EDGE_SMEM_F * 4);
    cudaFuncSetAttribute(node_kernel, cudaFuncAttributeMaxDynamicSharedMemorySize,
                         NODE_SMEM_F * 4);
    cudaFuncSetAttribute(prenode_kernel, cudaFuncAttributeMaxDynamicSharedMemorySize,
                         PRE_SMEM_F * 4);

    {
        int total = NL * K1 * N1 + NL * N1;
        pad_kernel<<<(total + 255) / 256, 256>>>(eW1, eb1);
    }
    embed_kernel<<<(N_NODES * HID + 255) / 256, 256>>>(x, pos, embedW, embedb);

    const int egrid = (N_EDGES + ETILE - 1) / ETILE;
    const int ngrid = (N_NODES + 63) / 64;
    for (int l = 0; l < NL; l++) {
        prenode_kernel<<<ngrid, TPB, PRE_SMEM_F * 4>>>(l);
        edge_kernel<<<egrid, TPB, EDGE_SMEM_F * 4>>>(ei, eattr, eW2, eb2, cW1, cb1,
                                                     cW2, cb2, l);
        node_kernel<<<ngrid, TPB, NODE_SMEM_F * 4>>>(nW1, nb1, nW2, nb2, l);
    }
    final_kernel<<<(N_NODES * 32 + 255) / 256, 256>>>(linW, linb, out);
}